// round 3
// baseline (speedup 1.0000x reference)
#include <cuda_runtime.h>
#include <cstdint>
#include <mma.h>

using namespace nvcuda;

// Problem constants
#define PB   64      // batch
#define PS   1024    // seq
#define PF   768     // features
#define PH   12      // heads
#define PDH  64      // head dim
#define PP2  64      // attended prefix length
#define NROW (PB * PP2)          // 4096 rows of the "active" matrix
#define HEADSZ 4096              // 64*64 per (b,h)
#define QKVSTRIDE (PB * PH * HEADSZ)   // 3,145,728

// Scratch: q/k/v [3][B][H][64][64] and attention output O [4096][768]
__device__ float g_qkv[3LL * QKVSTRIDE];
__device__ float g_o[(long long)NROW * PF];

// ---------------------------------------------------------------------------
// cp.async helpers
// ---------------------------------------------------------------------------
__device__ __forceinline__ void cp16(void* s, const void* g) {
    unsigned int sa = (unsigned int)__cvta_generic_to_shared(s);
    asm volatile("cp.async.cg.shared.global [%0], [%1], 16;\n" :: "r"(sa), "l"(g));
}
__device__ __forceinline__ void cp_commit() { asm volatile("cp.async.commit_group;\n"); }
template <int N>
__device__ __forceinline__ void cp_wait() { asm volatile("cp.async.wait_group %0;\n" :: "n"(N)); }

// ---------------------------------------------------------------------------
// TF32 WMMA GEMM, 128x128 block tile, BK=32, double-buffered cp.async.
// 256 threads = 8 warps as 2(M) x 4(N); warp tile 64x32.
// MODE 0: C[4096,2304] = Xw @ [Wq;Wk;Wv]^T + bias -> g_qkv[which][b][h][s][d]
//         plus interleaved tail-copy blocks (every 4th block).
// MODE 1: C[4096, 768] = O  @ Wo^T         + bo   -> d_out[b][s][c] (s < 64)
// ---------------------------------------------------------------------------
#define BM 128
#define BN 128
#define BK 32
#define LDA 44                       // BK + 12 pad: 16B-aligned rows, low-conflict
#define STAGE_F ((BM + BN) * LDA)    // 11264 floats per stage
#define SMEM_BYTES (2 * STAGE_F * 4) // 90112 B
#define LDC 132

#define COPY_BLOCKS 192
#define COPY_CHUNK  61440            // float4 per copy block (192*61440 = 64*960*192)

template <int MODE>
__global__ void __launch_bounds__(256) gemm_kernel(
    const float* __restrict__ A,
    const float* __restrict__ W0, const float* __restrict__ W1, const float* __restrict__ W2,
    const float* __restrict__ b0, const float* __restrict__ b1, const float* __restrict__ b2,
    float* __restrict__ Cout)
{
    extern __shared__ float sm[];
    const int tid = threadIdx.x;
    int bid = blockIdx.x;

    if (MODE == 0) {
        // Every 4th block is a tail-copy block (x[:,64:,:] -> out[:,64:,:])
        if ((bid & 3) == 3) {
            int cb = bid >> 2;                       // 0..191
            const float4* src = (const float4*)A;
            float4* dst = (float4*)Cout;
            const int PERB = (PS - PP2) * (PF / 4);  // 184320
            long long base = (long long)cb * COPY_CHUNK;
            #pragma unroll 4
            for (int t = tid; t < COPY_CHUNK; t += 256) {
                long long i = base + t;
                int b = (int)(i / PERB);
                int rem = (int)(i - (long long)b * PERB);
                long long off = (long long)b * (PS * (PF / 4)) + PP2 * (PF / 4) + rem;
                dst[off] = src[off];
            }
            return;
        }
        bid -= (bid >> 2);   // compact to gemm index 0..575
    }

    const int bx = bid & 31;          // M tile (4096/128 = 32)
    const int by = bid >> 5;          // N tile
    const int m0 = bx * BM;
    const int n0 = by * BN;

    const float* Aptr;
    const float* W;
    const float* bias;
    int nb;
    if (MODE == 0) {
        int wsel = n0 / 768;
        nb = n0 % 768;
        W    = (wsel == 0) ? W0 : (wsel == 1 ? W1 : W2);
        bias = (wsel == 0) ? b0 : (wsel == 1 ? b1 : b2);
        Aptr = A;
    } else {
        W = W0; bias = b0; nb = n0; Aptr = g_o;
    }

    const int lrow = tid >> 3;          // 0..31
    const int lcol = (tid & 7) * 4;     // 0,4,...,28

    // Stage loader: A tile 128x32 and B tile 128x32 via cp.async
    // (raw fp32; tf32 truncation happens inside the MMA)
    auto load_stage = [&](int s, int k0) {
        float* As = sm + s * STAGE_F;
        float* Bs = As + BM * LDA;
        #pragma unroll
        for (int p = 0; p < 4; p++) {
            int r = lrow + p * 32;
            int gm = m0 + r;
            const float* ga = (MODE == 0)
                ? Aptr + ((long long)(gm >> 6) * PS + (gm & 63)) * PF + k0 + lcol
                : Aptr + (long long)gm * PF + k0 + lcol;
            cp16(&As[r * LDA + lcol], ga);
        }
        #pragma unroll
        for (int p = 0; p < 4; p++) {
            int r = lrow + p * 32;
            const float* gb = W + (long long)(nb + r) * PF + k0 + lcol;
            cp16(&Bs[r * LDA + lcol], gb);
        }
    };

    wmma::fragment<wmma::accumulator, 16, 16, 8, float> acc[4][2];
    #pragma unroll
    for (int i = 0; i < 4; i++)
        #pragma unroll
        for (int j = 0; j < 2; j++) wmma::fill_fragment(acc[i][j], 0.0f);

    const int wid = tid >> 5;
    const int wm  = wid >> 2;    // 0..1
    const int wn  = wid & 3;     // 0..3

    load_stage(0, 0);
    cp_commit();

    const int NK = PF / BK;   // 24
    for (int k = 0; k < NK; k++) {
        if (k + 1 < NK) {
            load_stage((k + 1) & 1, (k + 1) * BK);
            cp_commit();
            cp_wait<1>();
        } else {
            cp_wait<0>();
        }
        __syncthreads();

        const float* As = sm + (k & 1) * STAGE_F;
        const float* Bs = As + BM * LDA;
        #pragma unroll
        for (int kk = 0; kk < BK; kk += 8) {
            wmma::fragment<wmma::matrix_a, 16, 16, 8, wmma::precision::tf32, wmma::row_major> af[4];
            wmma::fragment<wmma::matrix_b, 16, 16, 8, wmma::precision::tf32, wmma::col_major> bf[2];
            #pragma unroll
            for (int i = 0; i < 4; i++)
                wmma::load_matrix_sync(af[i], As + (wm * 64 + i * 16) * LDA + kk, LDA);
            #pragma unroll
            for (int j = 0; j < 2; j++)
                wmma::load_matrix_sync(bf[j], Bs + (wn * 32 + j * 16) * LDA + kk, LDA);
            #pragma unroll
            for (int i = 0; i < 4; i++)
                #pragma unroll
                for (int j = 0; j < 2; j++)
                    wmma::mma_sync(acc[i][j], af[i], bf[j], acc[i][j]);
        }
        __syncthreads();
    }

    // Epilogue: stage C in shared, add bias, scatter with layout mapping
    float* Cs = sm;
    #pragma unroll
    for (int i = 0; i < 4; i++)
        #pragma unroll
        for (int j = 0; j < 2; j++)
            wmma::store_matrix_sync(Cs + (wm * 64 + i * 16) * LDC + wn * 32 + j * 16,
                                    acc[i][j], LDC, wmma::mem_row_major);
    __syncthreads();

    const int c4 = (tid & 31) * 4;   // 0..124
    const int r0 = tid >> 5;         // 0..7
    float4 bv4;
    bv4.x = bias[nb + c4 + 0];
    bv4.y = bias[nb + c4 + 1];
    bv4.z = bias[nb + c4 + 2];
    bv4.w = bias[nb + c4 + 3];

    long long hbase = 0;
    if (MODE == 0) {
        int ncol = nb + c4;          // 0..767 within this W
        int h = ncol >> 6;
        int d = ncol & 63;
        int wsel = n0 / 768;
        hbase = (long long)wsel * QKVSTRIDE + (long long)h * HEADSZ + d;
    }

    #pragma unroll
    for (int p = 0; p < 16; p++) {
        int row = r0 + p * 8;
        int gm = m0 + row;
        float4 v = *reinterpret_cast<float4*>(Cs + row * LDC + c4);
        v.x += bv4.x; v.y += bv4.y; v.z += bv4.z; v.w += bv4.w;
        if (MODE == 0) {
            long long addr = hbase + (long long)((gm >> 6) * PH) * HEADSZ + (long long)(gm & 63) * 64;
            *reinterpret_cast<float4*>(&g_qkv[addr]) = v;
        } else {
            long long addr = ((long long)(gm >> 6) * PS + (gm & 63)) * PF + n0 + c4;
            *reinterpret_cast<float4*>(&Cout[addr]) = v;
        }
    }
}

// ---------------------------------------------------------------------------
// Attention core, one block per (b,h). 64x64 q,k,v tiles in smem.
// K tile XOR-swizzled so score-phase row reads are bank-conflict-free.
// ---------------------------------------------------------------------------
__global__ void __launch_bounds__(256) attn_kernel() {
    __shared__ float sq[64 * 64];   // q, later reused for v
    __shared__ float sk[64 * 64];   // k (swizzled)
    __shared__ float ss[64 * 64];   // scores -> attn weights

    const int b = blockIdx.x / PH;
    const int h = blockIdx.x % PH;
    const float* qg = g_qkv + (long long)(b * PH + h) * HEADSZ;
    const float* kg = qg + (long long)QKVSTRIDE;
    const float* vg = kg + (long long)QKVSTRIDE;

    const int tid  = threadIdx.x;
    const int lane = tid & 31;

    for (int t = tid; t < 1024; t += 256)
        reinterpret_cast<float4*>(sq)[t] = reinterpret_cast<const float4*>(qg)[t];
    for (int t = tid; t < 1024; t += 256) {
        int j = t >> 4, d4 = (t & 15) * 4;
        float4 v = reinterpret_cast<const float4*>(kg)[t];
        *reinterpret_cast<float4*>(&sk[j * 64 + (d4 ^ ((j & 7) << 3))]) = v;
    }
    __syncthreads();

    // scores[i][j] = dot(q_i, k_j) / 8
    #pragma unroll
    for (int t = 0; t < 16; t++) {
        int idx = tid + (t << 8);
        int i = idx >> 6, j = idx & 63;
        int sw = (j & 7) << 3;
        float s = 0.f;
        #pragma unroll
        for (int dd = 0; dd < 64; dd += 4) {
            float4 q4 = *reinterpret_cast<const float4*>(&sq[i * 64 + dd]);
            float4 k4 = *reinterpret_cast<const float4*>(&sk[j * 64 + (dd ^ sw)]);
            s += q4.x * k4.x + q4.y * k4.y + q4.z * k4.z + q4.w * k4.w;
        }
        ss[idx] = s * 0.125f;
    }
    __syncthreads();

    // row softmax: warp w handles rows [8w, 8w+8)
    {
        int w = tid >> 5;
        #pragma unroll
        for (int rr = 0; rr < 8; rr++) {
            int i = w * 8 + rr;
            float x0 = ss[i * 64 + lane];
            float x1 = ss[i * 64 + 32 + lane];
            float m = fmaxf(x0, x1);
            #pragma unroll
            for (int o = 16; o; o >>= 1) m = fmaxf(m, __shfl_xor_sync(0xffffffffu, m, o));
            float e0 = __expf(x0 - m), e1 = __expf(x1 - m);
            float sum = e0 + e1;
            #pragma unroll
            for (int o = 16; o; o >>= 1) sum += __shfl_xor_sync(0xffffffffu, sum, o);
            float inv = 1.0f / sum;
            ss[i * 64 + lane]      = e0 * inv;
            ss[i * 64 + 32 + lane] = e1 * inv;
        }
    }
    __syncthreads();

    // reload v over q
    for (int t = tid; t < 1024; t += 256)
        reinterpret_cast<float4*>(sq)[t] = reinterpret_cast<const float4*>(vg)[t];
    __syncthreads();

    // o[i][d] = sum_j attn[i][j] * v[j][d]; write as O[b*64+i][h*64+d]
    #pragma unroll
    for (int t = 0; t < 4; t++) {
        int g = tid + (t << 8);
        int i  = g >> 4;
        int d4 = (g & 15) * 4;
        float ox = 0.f, oy = 0.f, oz = 0.f, ow = 0.f;
        #pragma unroll 16
        for (int j = 0; j < 64; j++) {
            float a = ss[i * 64 + j];
            float4 v4 = *reinterpret_cast<const float4*>(&sq[j * 64 + d4]);
            ox += a * v4.x; oy += a * v4.y; oz += a * v4.z; ow += a * v4.w;
        }
        float4 o4; o4.x = ox; o4.y = oy; o4.z = oz; o4.w = ow;
        *reinterpret_cast<float4*>(&g_o[(long long)(b * 64 + i) * PF + h * 64 + d4]) = o4;
    }
}

// ---------------------------------------------------------------------------
extern "C" void kernel_launch(void* const* d_in, const int* in_sizes, int n_in,
                              void* d_out, int out_size) {
    const float* x  = (const float*)d_in[0];
    const float* Wq = (const float*)d_in[1];
    const float* bq = (const float*)d_in[2];
    const float* Wk = (const float*)d_in[3];
    const float* bk = (const float*)d_in[4];
    const float* Wv = (const float*)d_in[5];
    const float* bv = (const float*)d_in[6];
    const float* Wo = (const float*)d_in[7];
    const float* bo = (const float*)d_in[8];
    float* out = (float*)d_out;

    cudaFuncSetAttribute(gemm_kernel<0>, cudaFuncAttributeMaxDynamicSharedMemorySize, SMEM_BYTES);
    cudaFuncSetAttribute(gemm_kernel<1>, cudaFuncAttributeMaxDynamicSharedMemorySize, SMEM_BYTES);

    // 1) fused QKV projection (+bias) into scratch, with interleaved tail-copy blocks
    //    grid = 576 gemm blocks + 192 copy blocks, interleaved 3:1
    gemm_kernel<0><<<768, 256, SMEM_BYTES>>>(x, Wq, Wk, Wv, bq, bk, bv, out);

    // 2) attention per (b,h)
    attn_kernel<<<PB * PH, 256>>>();

    // 3) output projection (+bo) straight into d_out[:, :64, :]
    gemm_kernel<1><<<192, 256, SMEM_BYTES>>>(nullptr, Wo, nullptr, nullptr,
                                             bo, nullptr, nullptr, out);
}

// round 5
// speedup vs baseline: 2.0213x; 2.0213x over previous
#include <cuda_runtime.h>
#include <cstdint>

// Problem constants
#define PB   64
#define PS   1024
#define PF   768
#define PH   12
#define PP2  64
#define HEADSZ 4096
#define QKVSTRIDE (PB * PH * HEADSZ)   // 3,145,728

__device__ float g_qkv[3LL * QKVSTRIDE];
__device__ float g_o[4096LL * PF];

// ---------------------------------------------------------------------------
// PTX helpers (sm_80-era only: cp.async + mma.sync tf32)
// ---------------------------------------------------------------------------
__device__ __forceinline__ void cp16(void* s, const void* g) {
    unsigned sa = (unsigned)__cvta_generic_to_shared(s);
    asm volatile("cp.async.cg.shared.global [%0], [%1], 16;\n" :: "r"(sa), "l"(g));
}
__device__ __forceinline__ void cp_commit() { asm volatile("cp.async.commit_group;\n"); }
template <int N>
__device__ __forceinline__ void cp_wait() { asm volatile("cp.async.wait_group %0;\n" :: "n"(N)); }

__device__ __forceinline__ void mma_tf32(float* c, const unsigned* a, const unsigned* b) {
    asm volatile(
        "mma.sync.aligned.m16n8k8.row.col.f32.tf32.tf32.f32 "
        "{%0,%1,%2,%3}, {%4,%5,%6,%7}, {%8,%9}, {%0,%1,%2,%3};"
        : "+f"(c[0]), "+f"(c[1]), "+f"(c[2]), "+f"(c[3])
        : "r"(a[0]), "r"(a[1]), "r"(a[2]), "r"(a[3]), "r"(b[0]), "r"(b[1]));
}

// ---------------------------------------------------------------------------
// TF32 mma.sync GEMM. Block tile 128x128, BK=32, 2-stage cp.async.
// 256 threads = 8 warps as 2(M) x 4(N); warp tile 64x32.
// MODE 0: C[4096,2304] = Xw @ [Wq;Wk;Wv]^T + bias -> g_qkv[which][b][h][s][d]
// MODE 1: C[4096, 768] = O  @ Wo^T         + bo   -> d_out[b][s][c] (s < 64)
// ---------------------------------------------------------------------------
#define BK   32
#define LDK  36                         // 32 + 4: 16B-aligned rows, conflict-free frags
#define STAGEF ((128 + 128) * LDK)      // 9216 floats / stage
#define DSMEM  (2 * STAGEF * 4)         // 73728 B
#define NKI  (PF / BK)                  // 24

template <int MODE>
__global__ void __launch_bounds__(256, 2) tc_gemm(
    const float* __restrict__ A,
    const float* __restrict__ W0, const float* __restrict__ W1, const float* __restrict__ W2,
    const float* __restrict__ b0, const float* __restrict__ b1, const float* __restrict__ b2,
    float* __restrict__ Cout)
{
    extern __shared__ float sm[];

    const int tid  = threadIdx.x;
    const int wid  = tid >> 5;
    const int lane = tid & 31;
    const int wm   = wid >> 2;           // 0..1
    const int wn   = wid & 3;            // 0..3
    const int g    = lane >> 2;          // 0..7
    const int t4   = lane & 3;           // 0..3

    const int m0 = blockIdx.x * 128;
    const float* W; const float* bias; int nbw; int wsel = 0;
    if (MODE == 0) {
        wsel = blockIdx.y / 6;
        nbw  = (blockIdx.y % 6) * 128;
        W    = (wsel == 0) ? W0 : (wsel == 1 ? W1 : W2);
        bias = (wsel == 0) ? b0 : (wsel == 1 ? b1 : b2);
    } else {
        W = W0; bias = b0; nbw = blockIdx.y * 128;
    }
    const float* Ap = (MODE == 0) ? A : g_o;

    // Stage loader: A 128x32 + B 128x32, 4+4 cp16 per thread
    auto load_stage = [&](int buf, int k0) {
        float* As = sm + buf * STAGEF;
        float* Bs = As + 128 * LDK;
        #pragma unroll
        for (int p = 0; p < 4; p++) {
            int idx = tid + p * 256;
            int r = idx >> 3, c4 = (idx & 7) * 4;
            int gm = m0 + r;
            const float* ga = (MODE == 0)
                ? Ap + ((long long)(gm >> 6) * PS + (gm & 63)) * PF + k0 + c4
                : Ap + (long long)gm * PF + k0 + c4;
            cp16(&As[r * LDK + c4], ga);
        }
        #pragma unroll
        for (int p = 0; p < 4; p++) {
            int idx = tid + p * 256;
            int r = idx >> 3, c4 = (idx & 7) * 4;
            const float* gb = W + (long long)(nbw + r) * PF + k0 + c4;
            cp16(&Bs[r * LDK + c4], gb);
        }
    };

    float acc[4][4][4];
    #pragma unroll
    for (int mi = 0; mi < 4; mi++)
        #pragma unroll
        for (int ni = 0; ni < 4; ni++)
            #pragma unroll
            for (int q = 0; q < 4; q++) acc[mi][ni][q] = 0.0f;

    load_stage(0, 0);
    cp_commit();

    for (int i = 0; i < NKI; i++) {
        if (i + 1 < NKI) {
            load_stage((i + 1) & 1, (i + 1) * BK);
            cp_commit();
            cp_wait<1>();
        } else {
            cp_wait<0>();
        }
        __syncthreads();

        const float* As = sm + (i & 1) * STAGEF;
        const float* Bs = As + 128 * LDK;
        const float* ab = As + (wm * 64 + g) * LDK + t4;
        const float* bb = Bs + (wn * 32 + g) * LDK + t4;

        #pragma unroll
        for (int kk = 0; kk < BK; kk += 8) {
            unsigned af[4][4];
            #pragma unroll
            for (int mi = 0; mi < 4; mi++) {
                const float* p = ab + mi * 16 * LDK + kk;
                af[mi][0] = __float_as_uint(p[0]);
                af[mi][1] = __float_as_uint(p[8 * LDK]);
                af[mi][2] = __float_as_uint(p[4]);
                af[mi][3] = __float_as_uint(p[8 * LDK + 4]);
            }
            unsigned bf[4][2];
            #pragma unroll
            for (int ni = 0; ni < 4; ni++) {
                const float* p = bb + ni * 8 * LDK + kk;
                bf[ni][0] = __float_as_uint(p[0]);
                bf[ni][1] = __float_as_uint(p[4]);
            }
            #pragma unroll
            for (int mi = 0; mi < 4; mi++)
                #pragma unroll
                for (int ni = 0; ni < 4; ni++)
                    mma_tf32(acc[mi][ni], af[mi], bf[ni]);
        }
        __syncthreads();
    }

    // Bias per ni (float2, col pair this thread owns)
    float2 bfrag[4];
    #pragma unroll
    for (int ni = 0; ni < 4; ni++)
        bfrag[ni] = *reinterpret_cast<const float2*>(bias + nbw + wn * 32 + ni * 8 + t4 * 2);

    // Epilogue: direct global float2 stores from accumulators
    #pragma unroll
    for (int mi = 0; mi < 4; mi++) {
        #pragma unroll
        for (int half = 0; half < 2; half++) {
            int gm = m0 + wm * 64 + mi * 16 + g + half * 8;
            int bb_ = gm >> 6, ss_ = gm & 63;
            #pragma unroll
            for (int ni = 0; ni < 4; ni++) {
                int n = nbw + wn * 32 + ni * 8 + t4 * 2;
                float2 v;
                v.x = acc[mi][ni][half * 2 + 0] + bfrag[ni].x;
                v.y = acc[mi][ni][half * 2 + 1] + bfrag[ni].y;
                if (MODE == 0) {
                    int h = n >> 6, d = n & 63;
                    float* dst = g_qkv + (long long)wsel * QKVSTRIDE
                               + (long long)(bb_ * PH + h) * HEADSZ + ss_ * 64 + d;
                    *reinterpret_cast<float2*>(dst) = v;
                } else {
                    float* dst = Cout + ((long long)bb_ * PS + ss_) * PF + n;
                    *reinterpret_cast<float2*>(dst) = v;
                }
            }
        }
    }
}

// ---------------------------------------------------------------------------
// Attention (blocks 0..767) + tail copy (blocks 768..1727).
// ---------------------------------------------------------------------------
#define NCOPY 960
#define CCHUNK 12288    // float4 per copy block; 960*12288 = 64*960*192

__global__ void __launch_bounds__(256) attn_copy_kernel(const float4* __restrict__ x,
                                                        float4* __restrict__ out) {
    __shared__ float sq[64 * 64];
    __shared__ float sk[64 * 64];
    __shared__ float ss[64 * 64];

    const int tid = threadIdx.x;

    if (blockIdx.x >= PB * PH) {
        int cb = blockIdx.x - PB * PH;
        const int PERB = (PS - PP2) * (PF / 4);        // 184320
        int base = cb * CCHUNK;
        #pragma unroll 4
        for (int t = tid; t < CCHUNK; t += 256) {
            int i = base + t;
            int b = i / PERB;
            int rem = i - b * PERB;
            long long off = (long long)b * (PS * (PF / 4)) + PP2 * (PF / 4) + rem;
            out[off] = x[off];
        }
        return;
    }

    const int b = blockIdx.x / PH;
    const int h = blockIdx.x % PH;
    const float* qg = g_qkv + (long long)(b * PH + h) * HEADSZ;
    const float* kg = qg + (long long)QKVSTRIDE;
    const float* vg = kg + (long long)QKVSTRIDE;
    const int lane = tid & 31;

    for (int t = tid; t < 1024; t += 256)
        reinterpret_cast<float4*>(sq)[t] = reinterpret_cast<const float4*>(qg)[t];
    for (int t = tid; t < 1024; t += 256) {
        int j = t >> 4, d4 = (t & 15) * 4;
        float4 v = reinterpret_cast<const float4*>(kg)[t];
        *reinterpret_cast<float4*>(&sk[j * 64 + (d4 ^ ((j & 7) << 3))]) = v;
    }
    __syncthreads();

    #pragma unroll
    for (int t = 0; t < 16; t++) {
        int idx = tid + (t << 8);
        int i = idx >> 6, j = idx & 63;
        int sw = (j & 7) << 3;
        float s = 0.f;
        #pragma unroll
        for (int dd = 0; dd < 64; dd += 4) {
            float4 q4 = *reinterpret_cast<const float4*>(&sq[i * 64 + dd]);
            float4 k4 = *reinterpret_cast<const float4*>(&sk[j * 64 + (dd ^ sw)]);
            s += q4.x * k4.x + q4.y * k4.y + q4.z * k4.z + q4.w * k4.w;
        }
        ss[idx] = s * 0.125f;
    }
    __syncthreads();

    {
        int w = tid >> 5;
        #pragma unroll
        for (int rr = 0; rr < 8; rr++) {
            int i = w * 8 + rr;
            float x0 = ss[i * 64 + lane];
            float x1 = ss[i * 64 + 32 + lane];
            float m = fmaxf(x0, x1);
            #pragma unroll
            for (int o = 16; o; o >>= 1) m = fmaxf(m, __shfl_xor_sync(0xffffffffu, m, o));
            float e0 = __expf(x0 - m), e1 = __expf(x1 - m);
            float sum = e0 + e1;
            #pragma unroll
            for (int o = 16; o; o >>= 1) sum += __shfl_xor_sync(0xffffffffu, sum, o);
            float inv = 1.0f / sum;
            ss[i * 64 + lane]      = e0 * inv;
            ss[i * 64 + 32 + lane] = e1 * inv;
        }
    }
    __syncthreads();

    for (int t = tid; t < 1024; t += 256)
        reinterpret_cast<float4*>(sq)[t] = reinterpret_cast<const float4*>(vg)[t];
    __syncthreads();

    #pragma unroll
    for (int t = 0; t < 4; t++) {
        int gidx = tid + (t << 8);
        int i  = gidx >> 4;
        int d4 = (gidx & 15) * 4;
        float ox = 0.f, oy = 0.f, oz = 0.f, ow = 0.f;
        #pragma unroll 16
        for (int j = 0; j < 64; j++) {
            float a = ss[i * 64 + j];
            float4 v4 = *reinterpret_cast<const float4*>(&sq[j * 64 + d4]);
            ox += a * v4.x; oy += a * v4.y; oz += a * v4.z; ow += a * v4.w;
        }
        float4 o4; o4.x = ox; o4.y = oy; o4.z = oz; o4.w = ow;
        *reinterpret_cast<float4*>(&g_o[(long long)(b * 64 + i) * PF + h * 64 + d4]) = o4;
    }
}

// ---------------------------------------------------------------------------
extern "C" void kernel_launch(void* const* d_in, const int* in_sizes, int n_in,
                              void* d_out, int out_size) {
    const float* x  = (const float*)d_in[0];
    const float* Wq = (const float*)d_in[1];
    const float* bq = (const float*)d_in[2];
    const float* Wk = (const float*)d_in[3];
    const float* bk = (const float*)d_in[4];
    const float* Wv = (const float*)d_in[5];
    const float* bv = (const float*)d_in[6];
    const float* Wo = (const float*)d_in[7];
    const float* bo = (const float*)d_in[8];
    float* out = (float*)d_out;

    cudaFuncSetAttribute(tc_gemm<0>, cudaFuncAttributeMaxDynamicSharedMemorySize, DSMEM);
    cudaFuncSetAttribute(tc_gemm<1>, cudaFuncAttributeMaxDynamicSharedMemorySize, DSMEM);

    // 1) QKV projection (+bias) into g_qkv: N = 3 * 768, tiles 32 x 18
    tc_gemm<0><<<dim3(32, 18), 256, DSMEM>>>(x, Wq, Wk, Wv, bq, bk, bv, nullptr);

    // 2) attention per (b,h) + fused pass-through tail copy
    attn_copy_kernel<<<PB * PH + NCOPY, 256>>>((const float4*)x, (float4*)out);

    // 3) output projection (+bo) into d_out[:, :64, :]: tiles 32 x 6
    tc_gemm<1><<<dim3(32, 6), 256, DSMEM>>>(nullptr, Wo, nullptr, nullptr,
                                            bo, nullptr, nullptr, out);
}